// round 1
// baseline (speedup 1.0000x reference)
#include <cuda_runtime.h>
#include <cstdint>

// UniformShardedEmbeddingBags: B=1024, T=32, D=64, E=100000, L=50
// Bags are uniform (offsets = arange * L). bag = b*T + t, table = bag % T.
// out[bag, :] = sum_{j<L} W[feat[bag*L + j], bag % T, :]
//
// One warp per bag. 32 lanes x float2 = 256B coalesced per embedding row
// (rows are 256B-aligned). Indices fetched once per warp via 2 coalesced
// loads + shfl broadcast. Loop fully unrolled for memory-level parallelism.

namespace {
constexpr int kB = 1024;
constexpr int kT = 32;
constexpr int kD = 64;
constexpr int kL = 50;
constexpr int kNumBags = kB * kT;          // 32768
constexpr int kThreads = 256;              // 8 warps / block
constexpr int kBlocks = kNumBags / (kThreads / 32);  // 4096
}  // namespace

__global__ __launch_bounds__(kThreads)
void embedding_bag_kernel(const float* __restrict__ weights,
                          const int* __restrict__ features,
                          float* __restrict__ out) {
    const int warp = (blockIdx.x * kThreads + threadIdx.x) >> 5;
    const int lane = threadIdx.x & 31;
    // warp == bag index; grid sized exactly, no bounds check needed.

    const int table = warp & (kT - 1);
    const int* __restrict__ idxp = features + warp * kL;

    // Coalesced index fetch: lanes 0..31 get j=lane, lanes 0..17 get j=32+lane.
    const int i0 = idxp[lane];                       // always valid (L=50>32)
    const int i1 = (lane < kL - 32) ? idxp[32 + lane] : 0;

    // Base pointer into the table slice for this bag's table, as float2.
    // W element (e, t, d) at e*(T*D) + t*D + d floats.
    const float2* __restrict__ base =
        reinterpret_cast<const float2*>(weights) + (size_t)table * (kD / 2);
    constexpr size_t kRowStride2 = (size_t)kT * kD / 2;  // 1024 float2 per e

    float2 acc0 = make_float2(0.f, 0.f);
    float2 acc1 = make_float2(0.f, 0.f);

#pragma unroll
    for (int k = 0; k < 32; k += 2) {
        const int ia = __shfl_sync(0xffffffffu, i0, k);
        const int ib = __shfl_sync(0xffffffffu, i0, k + 1);
        const float2 va = __ldg(base + (size_t)ia * kRowStride2 + lane);
        const float2 vb = __ldg(base + (size_t)ib * kRowStride2 + lane);
        acc0.x += va.x; acc0.y += va.y;
        acc1.x += vb.x; acc1.y += vb.y;
    }
#pragma unroll
    for (int k = 0; k < 18; k += 2) {
        const int ia = __shfl_sync(0xffffffffu, i1, k);
        const int ib = __shfl_sync(0xffffffffu, i1, k + 1);
        const float2 va = __ldg(base + (size_t)ia * kRowStride2 + lane);
        const float2 vb = __ldg(base + (size_t)ib * kRowStride2 + lane);
        acc0.x += va.x; acc0.y += va.y;
        acc1.x += vb.x; acc1.y += vb.y;
    }

    float2 r;
    r.x = acc0.x + acc1.x;
    r.y = acc0.y + acc1.y;
    reinterpret_cast<float2*>(out)[(size_t)warp * (kD / 2) + lane] = r;
}

extern "C" void kernel_launch(void* const* d_in, const int* in_sizes, int n_in,
                              void* d_out, int out_size) {
    const float* weights  = (const float*)d_in[0];   // (E, T, D) fp32
    const int*   features = (const int*)d_in[1];     // (B*T*L,) int32
    // d_in[2]: offsets — uniform arange*L, encoded as compile-time constants.
    float* out = (float*)d_out;                      // (B, T, D) fp32

    embedding_bag_kernel<<<kBlocks, kThreads>>>(weights, features, out);
}

// round 2
// speedup vs baseline: 1.1044x; 1.1044x over previous
#include <cuda_runtime.h>
#include <cstdint>

// UniformShardedEmbeddingBags: B=1024, T=32, D=64, E=100000, L=50
// out[bag, :] = sum_{j<50} W[feat[bag*50 + j], bag % 32, :]
//
// One warp per bag; 32 lanes x float2 = 256B coalesced per row.
// R2 change: table-grouped bag ordering. Warp w handles
//   bag = ((w & 1023) << 5) | (w >> 10)
// so concurrently-resident warps (~7k) work on only ~7 of the 32 table
// slices at a time. Repeated indices within a table (~22% of draws) then
// hit in the 126MB L2 instead of going to DRAM.

namespace {
constexpr int kT = 32;
constexpr int kD = 64;
constexpr int kL = 50;
constexpr int kNumBags = 1024 * kT;                  // 32768
constexpr int kThreads = 256;                        // 8 warps / block
constexpr int kBlocks = kNumBags / (kThreads / 32);  // 4096
}  // namespace

__global__ __launch_bounds__(kThreads)
void embedding_bag_kernel(const float* __restrict__ weights,
                          const int* __restrict__ features,
                          float* __restrict__ out) {
    const int w = (blockIdx.x * kThreads + threadIdx.x) >> 5;
    const int lane = threadIdx.x & 31;

    // Table-grouped remap: warps [t*1024, (t+1)*1024) all pool table t.
    const int bag = ((w & 1023) << 5) | (w >> 10);
    const int table = w >> 10;  // == bag & 31

    const int* __restrict__ idxp = features + bag * kL;

    // Coalesced index fetch: lanes 0..31 get j=lane, lanes 0..17 get j=32+lane.
    const int i0 = idxp[lane];
    const int i1 = (lane < kL - 32) ? idxp[32 + lane] : 0;

    // Base pointer into this bag's table slice, as float2.
    const float2* __restrict__ base =
        reinterpret_cast<const float2*>(weights) + (size_t)table * (kD / 2);
    constexpr size_t kRowStride2 = (size_t)kT * kD / 2;  // 1024 float2 per e

    float2 acc0 = make_float2(0.f, 0.f);
    float2 acc1 = make_float2(0.f, 0.f);

#pragma unroll
    for (int k = 0; k < 32; k += 2) {
        const int ia = __shfl_sync(0xffffffffu, i0, k);
        const int ib = __shfl_sync(0xffffffffu, i0, k + 1);
        const float2 va = __ldg(base + (size_t)ia * kRowStride2 + lane);
        const float2 vb = __ldg(base + (size_t)ib * kRowStride2 + lane);
        acc0.x += va.x; acc0.y += va.y;
        acc1.x += vb.x; acc1.y += vb.y;
    }
#pragma unroll
    for (int k = 0; k < 18; k += 2) {
        const int ia = __shfl_sync(0xffffffffu, i1, k);
        const int ib = __shfl_sync(0xffffffffu, i1, k + 1);
        const float2 va = __ldg(base + (size_t)ia * kRowStride2 + lane);
        const float2 vb = __ldg(base + (size_t)ib * kRowStride2 + lane);
        acc0.x += va.x; acc0.y += va.y;
        acc1.x += vb.x; acc1.y += vb.y;
    }

    float2 r;
    r.x = acc0.x + acc1.x;
    r.y = acc0.y + acc1.y;
    reinterpret_cast<float2*>(out)[(size_t)bag * (kD / 2) + lane] = r;
}

extern "C" void kernel_launch(void* const* d_in, const int* in_sizes, int n_in,
                              void* d_out, int out_size) {
    const float* weights  = (const float*)d_in[0];   // (E, T, D) fp32
    const int*   features = (const int*)d_in[1];     // (B*T*L,) int32
    // d_in[2]: offsets — uniform arange*L, folded into compile-time constants.
    float* out = (float*)d_out;                      // (B, T, D) fp32

    embedding_bag_kernel<<<kBlocks, kThreads>>>(weights, features, out);
}